// round 7
// baseline (speedup 1.0000x reference)
#include <cuda_runtime.h>
#include <math.h>

#define BINSIZE      200
#define BINWIDTH     500
#define N_CLUSTERS   20
#define N_ROI_MAX    200
#define N_CELLS_MAX  100352   // 100000 rounded up to 16B multiple
#define GATHER_ITERS 4

// Precomputed log-density table: [n_roi, n_clusters, BINWIDTH]
__device__ float g_heights[N_ROI_MAX * N_CLUSTERS * BINWIDTH];
// labels compacted to uint8 (100KB -> L1-resident alongside gather lines)
__device__ __align__(16) unsigned char g_labels8[N_CELLS_MAX];

// ---------------------------------------------------------------------------
// Kernel 1 (fused): heights build (warp per row) + label int32->uint8 pack.
// ---------------------------------------------------------------------------
__global__ void __launch_bounds__(256) build_kernel(
    const float* __restrict__ baseline,
    const float* __restrict__ delta,
    const int*   __restrict__ regions_oi,
    const int*   __restrict__ labels,
    int n_rows, int n_clusters, int rowBlocks, int n_cells)
{
    if ((int)blockIdx.x < rowBlocks) {
        const int warp = (int)blockIdx.x * 8 + ((int)threadIdx.x >> 5);
        if (warp >= n_rows) return;
        const int lane = threadIdx.x & 31;
        const int roi = warp / n_clusters;
        const int cl  = warp - roi * n_clusters;
        const int region = regions_oi[roi];

        const float4* __restrict__ b4 = (const float4*)(baseline + (long long)region * BINWIDTH);
        const float4* __restrict__ d4 = (const float4*)(delta + ((long long)region * n_clusters + cl) * BINWIDTH);

        float4 v[4];
        float m = -INFINITY;
        #pragma unroll
        for (int it = 0; it < 4; it++) {
            const int idx = lane + it * 32;
            if (idx < 125) {
                float4 a = b4[idx];
                float4 d = d4[idx];
                v[it].x = a.x + d.x; v[it].y = a.y + d.y;
                v[it].z = a.z + d.z; v[it].w = a.w + d.w;
                m = fmaxf(m, fmaxf(fmaxf(v[it].x, v[it].y), fmaxf(v[it].z, v[it].w)));
            }
        }
        #pragma unroll
        for (int o = 16; o > 0; o >>= 1)
            m = fmaxf(m, __shfl_xor_sync(0xffffffffu, m, o));

        float s = 0.0f;
        #pragma unroll
        for (int it = 0; it < 4; it++) {
            const int idx = lane + it * 32;
            if (idx < 125) {
                s += __expf(v[it].x - m) + __expf(v[it].y - m)
                   + __expf(v[it].z - m) + __expf(v[it].w - m);
            }
        }
        #pragma unroll
        for (int o = 16; o > 0; o >>= 1)
            s += __shfl_xor_sync(0xffffffffu, s, o);

        const float sub = m + __logf(s) + logf((float)BINSIZE);

        float4* __restrict__ o4 = (float4*)(g_heights + (long long)warp * BINWIDTH);
        #pragma unroll
        for (int it = 0; it < 4; it++) {
            const int idx = lane + it * 32;
            if (idx < 125) {
                float4 h;
                h.x = v[it].x - sub; h.y = v[it].y - sub;
                h.z = v[it].z - sub; h.w = v[it].w - sub;
                o4[idx] = h;
            }
        }
    } else {
        const int b = (int)blockIdx.x - rowBlocks;
        const int t = b * 256 + (int)threadIdx.x;
        const int i0 = t * 4;
        if (i0 + 4 <= n_cells) {
            const int4 l = ((const int4*)labels)[t];
            uchar4 p;
            p.x = (unsigned char)l.x; p.y = (unsigned char)l.y;
            p.z = (unsigned char)l.z; p.w = (unsigned char)l.w;
            ((uchar4*)g_labels8)[t] = p;
        } else {
            for (int i = i0; i < n_cells; i++)
                g_labels8[i] = (unsigned char)labels[i];
        }
    }
}

// ---------------------------------------------------------------------------
// Kernel 2: per-fragment gather, 4 fragments/thread, grid-stride with
// software-pipelined prefetch of the chain-head loads (lcix, lrix).
// Streaming traffic uses .cs (evict-first); labels byte table stays
// L1-resident; full 228KB L1 carveout (no smem).
// ---------------------------------------------------------------------------
__global__ void __launch_bounds__(256) gather_kernel(
    const int*   __restrict__ coords,      // [n, 2]
    const int*   __restrict__ lrix,        // [n]
    const int*   __restrict__ lcix,        // [n]
    const float* __restrict__ inside,      // [1]
    float*       __restrict__ out,         // [n, 2]
    int n, int n_groups)
{
    const float x    = inside[0];
    const float l1p  = log1pf(expf(-x));
    const float lpIn  = -l1p     - logf((float)BINWIDTH);
    const float lpOut = -x - l1p - logf((float)(100000 - BINWIDTH));

    const int stride = gridDim.x * blockDim.x;
    int g = blockIdx.x * blockDim.x + threadIdx.x;

    // Prologue: prefetch chain-head data for first iteration.
    int4 qq, rr;
    bool full = (g * 4 + 4 <= n);
    if (full) {
        qq = __ldcs((const int4*)lcix + g);
        rr = __ldcs((const int4*)lrix + g);
    }

    while (g < n_groups) {
        const int gn = g + stride;
        const bool full_n = (gn * 4 + 4 <= n) && (gn < n_groups);
        int4 qq_n, rr_n;
        if (full_n) {                      // prefetch next iteration's heads
            qq_n = __ldcs((const int4*)lcix + gn);
            rr_n = __ldcs((const int4*)lrix + gn);
        }

        if (full) {
            // coords issued here; ~2 gather latencies available to complete
            const int4 c0 = __ldcs((const int4*)coords + g * 2 + 0);
            const int4 c1 = __ldcs((const int4*)coords + g * 2 + 1);

            // label gathers start immediately (qq already in registers)
            const int lab0 = __ldg(&g_labels8[qq.x]);
            const int lab1 = __ldg(&g_labels8[qq.y]);
            const int lab2 = __ldg(&g_labels8[qq.z]);
            const int lab3 = __ldg(&g_labels8[qq.w]);

            const int bl0 = (int)((unsigned)c0.x / BINSIZE), br0 = (int)((unsigned)c0.y / BINSIZE);
            const int bl1 = (int)((unsigned)c0.z / BINSIZE), br1 = (int)((unsigned)c0.w / BINSIZE);
            const int bl2 = (int)((unsigned)c1.x / BINSIZE), br2 = (int)((unsigned)c1.y / BINSIZE);
            const int bl3 = (int)((unsigned)c1.z / BINSIZE), br3 = (int)((unsigned)c1.w / BINSIZE);

            const float L0 = __ldg(&g_heights[(rr.x * N_CLUSTERS + lab0) * BINWIDTH + bl0]);
            const float L1 = __ldg(&g_heights[(rr.y * N_CLUSTERS + lab1) * BINWIDTH + bl1]);
            const float L2 = __ldg(&g_heights[(rr.z * N_CLUSTERS + lab2) * BINWIDTH + bl2]);
            const float L3 = __ldg(&g_heights[(rr.w * N_CLUSTERS + lab3) * BINWIDTH + bl3]);

            float4 o0, o1;
            o0.x = L0; o0.y = (bl0 == br0) ? lpIn : lpOut;
            o0.z = L1; o0.w = (bl1 == br1) ? lpIn : lpOut;
            o1.x = L2; o1.y = (bl2 == br2) ? lpIn : lpOut;
            o1.z = L3; o1.w = (bl3 == br3) ? lpIn : lpOut;
            __stcs((float4*)out + g * 2 + 0, o0);
            __stcs((float4*)out + g * 2 + 1, o1);
        } else {
            // tail group: scalar path
            for (int i = g * 4; i < n; i++) {
                const int cx = coords[i * 2 + 0];
                const int cy = coords[i * 2 + 1];
                const int bl = (int)((unsigned)cx / BINSIZE), br = (int)((unsigned)cy / BINSIZE);
                const int lab = g_labels8[lcix[i]];
                const int rg = lrix[i];
                out[i * 2 + 0] = g_heights[(rg * N_CLUSTERS + lab) * BINWIDTH + bl];
                out[i * 2 + 1] = (bl == br) ? lpIn : lpOut;
            }
        }

        qq = qq_n; rr = rr_n; full = full_n;
        g = gn;
    }
}

// ---------------------------------------------------------------------------
extern "C" void kernel_launch(void* const* d_in, const int* in_sizes, int n_in,
                              void* d_out, int out_size)
{
    const float* baseline = (const float*)d_in[0];
    const float* delta    = (const float*)d_in[1];
    const float* inside   = (const float*)d_in[2];
    const int*   regions  = (const int*)d_in[3];
    const int*   coords   = (const int*)d_in[4];
    const int*   lrix     = (const int*)d_in[5];
    const int*   lcix     = (const int*)d_in[6];
    const int*   labels   = (const int*)d_in[7];
    float*       out      = (float*)d_out;

    const int n_roi      = in_sizes[3];
    const int n          = in_sizes[5];
    const int n_cells    = in_sizes[7];
    const int n_regions  = in_sizes[0] / BINWIDTH;
    const int n_clusters = (n_regions > 0) ? (in_sizes[1] / (n_regions * BINWIDTH)) : N_CLUSTERS;

    const int n_rows    = n_roi * n_clusters;
    const int rowBlocks = (n_rows + 7) / 8;
    const int packBlocks = (n_cells + 1023) / 1024;
    build_kernel<<<rowBlocks + packBlocks, 256>>>(
        baseline, delta, regions, labels, n_rows, n_clusters, rowBlocks, n_cells);

    const int n_groups = (n + 3) / 4;
    const int blocks   = (n_groups + 256 * GATHER_ITERS - 1) / (256 * GATHER_ITERS);
    gather_kernel<<<blocks, 256>>>(coords, lrix, lcix, inside, out, n, n_groups);
}

// round 8
// speedup vs baseline: 1.5487x; 1.5487x over previous
#include <cuda_runtime.h>
#include <math.h>

#define BINSIZE      200
#define BINWIDTH     500
#define N_CLUSTERS   20
#define N_ROI_MAX    200
#define N_CELLS_MAX  100352   // 100000 rounded up to 16B multiple

// Precomputed log-density table: [n_roi, n_clusters, BINWIDTH]
__device__ float g_heights[N_ROI_MAX * N_CLUSTERS * BINWIDTH];
// labels compacted to uint8 (100KB -> L1/L2-resident)
__device__ __align__(16) unsigned char g_labels8[N_CELLS_MAX];
// sink to keep the L2-warming loads alive (never actually written)
__device__ int g_sink;

// ---------------------------------------------------------------------------
// Kernel 1 (fused, three block ranges):
//   [0, rowBlocks)                : heights build (one warp per (roi,cluster))
//   [rowBlocks, +packBlocks)      : labels int32 -> uint8 pack
//   [.., +warmBlocks)             : L2 warm of coords/lrix/lcix streams
// ---------------------------------------------------------------------------
__global__ void __launch_bounds__(256) build_kernel(
    const float* __restrict__ baseline,
    const float* __restrict__ delta,
    const int*   __restrict__ regions_oi,
    const int*   __restrict__ labels,
    const int*   __restrict__ coords,     // [n,2]  (warm)
    const int*   __restrict__ lrix,       // [n]    (warm)
    const int*   __restrict__ lcix,       // [n]    (warm)
    int n_rows, int n_clusters, int rowBlocks, int packBlocks,
    int n_cells, int n)
{
    if ((int)blockIdx.x < rowBlocks) {
        const int warp = (int)blockIdx.x * 8 + ((int)threadIdx.x >> 5);
        if (warp >= n_rows) return;
        const int lane = threadIdx.x & 31;
        const int roi = warp / n_clusters;
        const int cl  = warp - roi * n_clusters;
        const int region = regions_oi[roi];

        const float4* __restrict__ b4 = (const float4*)(baseline + (long long)region * BINWIDTH);
        const float4* __restrict__ d4 = (const float4*)(delta + ((long long)region * n_clusters + cl) * BINWIDTH);

        float4 v[4];
        float m = -INFINITY;
        #pragma unroll
        for (int it = 0; it < 4; it++) {
            const int idx = lane + it * 32;
            if (idx < 125) {
                float4 a = b4[idx];
                float4 d = d4[idx];
                v[it].x = a.x + d.x; v[it].y = a.y + d.y;
                v[it].z = a.z + d.z; v[it].w = a.w + d.w;
                m = fmaxf(m, fmaxf(fmaxf(v[it].x, v[it].y), fmaxf(v[it].z, v[it].w)));
            }
        }
        #pragma unroll
        for (int o = 16; o > 0; o >>= 1)
            m = fmaxf(m, __shfl_xor_sync(0xffffffffu, m, o));

        float s = 0.0f;
        #pragma unroll
        for (int it = 0; it < 4; it++) {
            const int idx = lane + it * 32;
            if (idx < 125) {
                s += __expf(v[it].x - m) + __expf(v[it].y - m)
                   + __expf(v[it].z - m) + __expf(v[it].w - m);
            }
        }
        #pragma unroll
        for (int o = 16; o > 0; o >>= 1)
            s += __shfl_xor_sync(0xffffffffu, s, o);

        const float sub = m + __logf(s) + logf((float)BINSIZE);

        float4* __restrict__ o4 = (float4*)(g_heights + (long long)warp * BINWIDTH);
        #pragma unroll
        for (int it = 0; it < 4; it++) {
            const int idx = lane + it * 32;
            if (idx < 125) {
                float4 h;
                h.x = v[it].x - sub; h.y = v[it].y - sub;
                h.z = v[it].z - sub; h.w = v[it].w - sub;
                o4[idx] = h;
            }
        }
    } else if ((int)blockIdx.x < rowBlocks + packBlocks) {
        const int b = (int)blockIdx.x - rowBlocks;
        const int t = b * 256 + (int)threadIdx.x;
        const int i0 = t * 4;
        if (i0 + 4 <= n_cells) {
            const int4 l = ((const int4*)labels)[t];
            uchar4 p;
            p.x = (unsigned char)l.x; p.y = (unsigned char)l.y;
            p.z = (unsigned char)l.z; p.w = (unsigned char)l.w;
            ((uchar4*)g_labels8)[t] = p;
        } else {
            for (int i = i0; i < n_cells; i++)
                g_labels8[i] = (unsigned char)labels[i];
        }
    } else {
        // L2 warm: touch-read coords (2n ints), lrix (n), lcix (n) as int4.
        // Total vectors = n (= n/2 + n/4 + n/4).
        const int b = (int)blockIdx.x - rowBlocks - packBlocks;
        const int t = b * 256 + (int)threadIdx.x;
        const int nv_c = n >> 1;    // int4 count in coords
        const int nv_i = n >> 2;    // int4 count in lrix / lcix
        int acc = 0;
        if (t < nv_c) {
            const int4 a = __ldcg((const int4*)coords + t);
            acc += a.x ^ a.w;
        }
        if (t < nv_i) {
            const int4 a = __ldcg((const int4*)lrix + t);
            const int4 b2 = __ldcg((const int4*)lcix + t);
            acc += a.x ^ b2.x;
        }
        // impossible-to-predict dead store keeps the loads live
        if (acc == 0x7f3a5c21) g_sink = acc;
    }
}

// ---------------------------------------------------------------------------
// Kernel 2: per-fragment gather, 4 fragments/thread (R6 config, proven).
// Streaming traffic uses .cs (evict-first); labels byte table L1-resident;
// full 228KB L1 carveout (no smem).
// ---------------------------------------------------------------------------
__global__ void __launch_bounds__(256) gather_kernel(
    const int*   __restrict__ coords,      // [n, 2]
    const int*   __restrict__ lrix,        // [n]
    const int*   __restrict__ lcix,        // [n]
    const float* __restrict__ inside,      // [1]
    float*       __restrict__ out,         // [n, 2]
    int n)
{
    const int g  = blockIdx.x * blockDim.x + threadIdx.x;
    const int i0 = g * 4;
    if (i0 >= n) return;

    const float x    = inside[0];
    const float l1p  = log1pf(expf(-x));
    const float lpIn  = -l1p     - logf((float)BINWIDTH);
    const float lpOut = -x - l1p - logf((float)(100000 - BINWIDTH));

    if (i0 + 4 <= n) {
        const int4 c0 = __ldcs((const int4*)coords + g * 2 + 0);
        const int4 c1 = __ldcs((const int4*)coords + g * 2 + 1);
        const int4 rr = __ldcs((const int4*)lrix + g);
        const int4 qq = __ldcs((const int4*)lcix + g);

        const int lab0 = __ldg(&g_labels8[qq.x]);
        const int lab1 = __ldg(&g_labels8[qq.y]);
        const int lab2 = __ldg(&g_labels8[qq.z]);
        const int lab3 = __ldg(&g_labels8[qq.w]);

        const int bl0 = (int)((unsigned)c0.x / BINSIZE), br0 = (int)((unsigned)c0.y / BINSIZE);
        const int bl1 = (int)((unsigned)c0.z / BINSIZE), br1 = (int)((unsigned)c0.w / BINSIZE);
        const int bl2 = (int)((unsigned)c1.x / BINSIZE), br2 = (int)((unsigned)c1.y / BINSIZE);
        const int bl3 = (int)((unsigned)c1.z / BINSIZE), br3 = (int)((unsigned)c1.w / BINSIZE);

        const float L0 = __ldg(&g_heights[(rr.x * N_CLUSTERS + lab0) * BINWIDTH + bl0]);
        const float L1 = __ldg(&g_heights[(rr.y * N_CLUSTERS + lab1) * BINWIDTH + bl1]);
        const float L2 = __ldg(&g_heights[(rr.z * N_CLUSTERS + lab2) * BINWIDTH + bl2]);
        const float L3 = __ldg(&g_heights[(rr.w * N_CLUSTERS + lab3) * BINWIDTH + bl3]);

        float4 o0, o1;
        o0.x = L0; o0.y = (bl0 == br0) ? lpIn : lpOut;
        o0.z = L1; o0.w = (bl1 == br1) ? lpIn : lpOut;
        o1.x = L2; o1.y = (bl2 == br2) ? lpIn : lpOut;
        o1.z = L3; o1.w = (bl3 == br3) ? lpIn : lpOut;
        __stcs((float4*)out + g * 2 + 0, o0);
        __stcs((float4*)out + g * 2 + 1, o1);
    } else {
        for (int i = i0; i < n; i++) {
            const int cx = coords[i * 2 + 0];
            const int cy = coords[i * 2 + 1];
            const int bl = (int)((unsigned)cx / BINSIZE), br = (int)((unsigned)cy / BINSIZE);
            const int lab = g_labels8[lcix[i]];
            const int rg = lrix[i];
            out[i * 2 + 0] = g_heights[(rg * N_CLUSTERS + lab) * BINWIDTH + bl];
            out[i * 2 + 1] = (bl == br) ? lpIn : lpOut;
        }
    }
}

// ---------------------------------------------------------------------------
extern "C" void kernel_launch(void* const* d_in, const int* in_sizes, int n_in,
                              void* d_out, int out_size)
{
    const float* baseline = (const float*)d_in[0];
    const float* delta    = (const float*)d_in[1];
    const float* inside   = (const float*)d_in[2];
    const int*   regions  = (const int*)d_in[3];
    const int*   coords   = (const int*)d_in[4];
    const int*   lrix     = (const int*)d_in[5];
    const int*   lcix     = (const int*)d_in[6];
    const int*   labels   = (const int*)d_in[7];
    float*       out      = (float*)d_out;

    const int n_roi      = in_sizes[3];
    const int n          = in_sizes[5];
    const int n_cells    = in_sizes[7];
    const int n_regions  = in_sizes[0] / BINWIDTH;
    const int n_clusters = (n_regions > 0) ? (in_sizes[1] / (n_regions * BINWIDTH)) : N_CLUSTERS;

    const int n_rows     = n_roi * n_clusters;
    const int rowBlocks  = (n_rows + 7) / 8;
    const int packBlocks = (n_cells + 1023) / 1024;
    // warm: one thread per int4 of coords (n/2 vectors dominates lrix/lcix n/4)
    const int warmBlocks = ((n >> 1) + 255) / 256;
    build_kernel<<<rowBlocks + packBlocks + warmBlocks, 256>>>(
        baseline, delta, regions, labels, coords, lrix, lcix,
        n_rows, n_clusters, rowBlocks, packBlocks, n_cells, n);

    const int n_groups = (n + 3) / 4;
    const int blocks   = (n_groups + 255) / 256;
    gather_kernel<<<blocks, 256>>>(coords, lrix, lcix, inside, out, n);
}